// round 9
// baseline (speedup 1.0000x reference)
#include <cuda_runtime.h>
#include <math.h>
#include <stdint.h>

#define NS   65536
#define DD   256
#define KK   10
#define NCH  14          // sample chunks per class -> 140 CTAs (one wave)
#define SORT_T 4096      // 16 blocks x 256 sorting threads
#define SPT  16          // samples per sorting thread
#define NTILE 3          // (0,0),(0,1),(1,1) 128x128 tiles of 256x256
#define TRI_N 32896      // 256*257/2
#define SSTRIDE 264      // smem sample stride in floats (256+8): bank-perfect

typedef unsigned long long ull;

// ----------------- device scratch (static globals; no allocation) -----------------
__device__ int    g_is64;
__device__ int    g_hist[KK * SORT_T];
__device__ int    g_count[KK];
__device__ int    g_off[KK];
__device__ int    g_perm[NS];
__device__ float  g_part[NCH * KK * NTILE][16384];   // ~27.5 MB partial tiles
__device__ float  g_cov[KK][DD * DD];
__device__ float  g_gram[DD * DD];
__device__ double g_logdet[KK + 1];                  // [0]=gram, [1..10]=classes

// ----------------- f32x2 helpers (packed fp32 FMA, plain sm_103-legal) -----------------
__device__ __forceinline__ ull pk2(float x, float y) {
    ull d;
    asm("mov.b64 %0, {%1, %2};" : "=l"(d)
        : "r"(__float_as_uint(x)), "r"(__float_as_uint(y)));
    return d;
}
__device__ __forceinline__ ull ffma2(ull a, ull b, ull c) {
    ull d;
    asm("fma.rn.f32x2 %0, %1, %2, %3;" : "=l"(d) : "l"(a), "l"(b), "l"(c));
    return d;
}
__device__ __forceinline__ float2 upk2(ull d) {
    unsigned int lo, hi;
    asm("mov.b64 {%0, %1}, %2;" : "=r"(lo), "=r"(hi) : "l"(d));
    return make_float2(__uint_as_float(lo), __uint_as_float(hi));
}

__device__ __forceinline__ int tri(int i) { return (i * (i + 1)) >> 1; }

__device__ __forceinline__ uint32_t cvt_tf32(float f) {
    uint32_t r;
    asm("cvt.rna.tf32.f32 %0, %1;" : "=r"(r) : "f"(f));
    return r;
}
__device__ __forceinline__ void mma_tf32(float d[4], const uint32_t a[4],
                                         uint32_t b0, uint32_t b1) {
    asm volatile(
        "mma.sync.aligned.m16n8k8.row.col.f32.tf32.tf32.f32 "
        "{%0,%1,%2,%3}, {%4,%5,%6,%7}, {%8,%9}, {%0,%1,%2,%3};"
        : "+f"(d[0]), "+f"(d[1]), "+f"(d[2]), "+f"(d[3])
        : "r"(a[0]), "r"(a[1]), "r"(a[2]), "r"(a[3]), "r"(b0), "r"(b1));
}

// ----------------- 0. label dtype detection (int64 vs int32) -----------------
__global__ void k_detect(const int* __restrict__ Y) {
    __shared__ int bad;
    if (threadIdx.x == 0) bad = 0;
    __syncthreads();
    int viol = 0;
    for (int w = 0; w < 8; ++w) {
        int idx = threadIdx.x * 8 + w;
        int v = Y[idx];
        if (idx & 1) { if (v != 0) viol = 1; }
        else         { if (v < 0 || v >= KK) viol = 1; }
    }
    if (viol) atomicOr(&bad, 1);
    __syncthreads();
    if (threadIdx.x == 0) g_is64 = bad ? 0 : 1;
}

// ----------------- 1-4. deterministic stable counting sort of labels -----------------
__global__ void k_hist(const int* __restrict__ Y) {
    int t = blockIdx.x * blockDim.x + threadIdx.x;
    int cnt[KK];
#pragma unroll
    for (int c = 0; c < KK; ++c) cnt[c] = 0;
    int is64 = g_is64;
    int base = t * SPT;
    for (int q = 0; q < SPT; ++q) {
        int i = base + q;
        int lab = is64 ? Y[2 * i] : Y[i];
        cnt[lab]++;
    }
#pragma unroll
    for (int c = 0; c < KK; ++c) g_hist[c * SORT_T + t] = cnt[c];
}

__global__ void k_scan() {
    int c = blockIdx.x, tid = threadIdx.x;
    int* h = g_hist + c * SORT_T;
    int loc[16];
    int base = tid * 16;
    int tsum = 0;
#pragma unroll
    for (int q = 0; q < 16; ++q) { loc[q] = h[base + q]; tsum += loc[q]; }
    __shared__ int sh[256];
    sh[tid] = tsum;
    __syncthreads();
    for (int st = 1; st < 256; st <<= 1) {
        int v = 0;
        if (tid >= st) v = sh[tid - st];
        __syncthreads();
        if (tid >= st) sh[tid] += v;
        __syncthreads();
    }
    int run = sh[tid] - tsum;
#pragma unroll
    for (int q = 0; q < 16; ++q) { h[base + q] = run; run += loc[q]; }
    if (tid == 255) g_count[c] = sh[255];
}

__global__ void k_offs() {
    if (threadIdx.x == 0 && blockIdx.x == 0) {
        int a = 0;
        for (int c = 0; c < KK; ++c) { g_off[c] = a; a += g_count[c]; }
    }
}

__global__ void k_scat(const int* __restrict__ Y) {
    int t = blockIdx.x * blockDim.x + threadIdx.x;
    int cnt[KK];
#pragma unroll
    for (int c = 0; c < KK; ++c) cnt[c] = 0;
    int is64 = g_is64;
    int base = t * SPT;
    for (int q = 0; q < SPT; ++q) {
        int i = base + q;
        int lab = is64 ? Y[2 * i] : Y[i];
        int pos = g_off[lab] + g_hist[lab * SORT_T + t] + cnt[lab];
        cnt[lab]++;
        g_perm[pos] = i;
    }
}

// ----------------- 5. grouped SYRK via mma.sync tf32 (valid on plain sm_103) ------
// Block b: ch=b/KK, class k=b%KK. For each of 3 tiles: warps tile 128x128 as
// 4x2 regions of 32x64. smem: sample-major tf32 tile, stride 264 floats
// -> fragment LDS bank index = (8*samp + feat) mod 32 = 8*tig + gid: conflict-free.
__global__ void __launch_bounds__(256, 1) k_syrk_mma(const float* __restrict__ X) {
    __shared__ uint32_t S[2][16 * SSTRIDE];

    int tid = threadIdx.x, wid = tid >> 5, lane = tid & 31;
    int gid = lane >> 2, tig = lane & 3;

    int b = blockIdx.x;
    int ch = b / KK, k = b % KK;
    int off = g_off[k], cnt = g_count[k];
    int len = (cnt + NCH - 1) / NCH;
    int sb = off + ch * len;
    int se = off + cnt;
    if (sb + len < se) se = sb + len;
    int nblk = (se > sb) ? (se - sb + 15) / 16 : 0;

    const float4* X4 = (const float4*)X;

    int mw = wid >> 1, nw = wid & 1;       // 4 x 2 warp grid
    int MbL = 32 * mw;

    for (int t = 0; t < NTILE; ++t) {
        int flo4 = (t == 2) ? 32 : 0;        // feature float4 offset in X row
        int nf = (t == 1) ? 256 : 128;
        int nf4 = nf >> 2;
        int nit = nf4 * 16 / 256;            // float4s per thread: 2 or 4
        int NbL = ((t == 1) ? 128 : 0) + 64 * nw;

        float acc[2][8][4];
#pragma unroll
        for (int a = 0; a < 2; ++a)
#pragma unroll
            for (int n = 0; n < 8; ++n)
#pragma unroll
                for (int c = 0; c < 4; ++c) acc[a][n][c] = 0.f;

        float4 vreg[4];

        // prologue: load block 0
        if (nblk > 0) {
            for (int l = 0; l < nit; ++l) {
                int idx = tid + 256 * l;
                int samp = idx / nf4, f4 = idx % nf4;
                int si = sb + samp;
                int sp = (si < se) ? g_perm[si] : -1;
                vreg[l] = (sp >= 0) ? X4[(size_t)sp * 64 + flo4 + f4]
                                    : make_float4(0.f, 0.f, 0.f, 0.f);
            }
            for (int l = 0; l < nit; ++l) {
                int idx = tid + 256 * l;
                int samp = idx / nf4, f4 = idx % nf4;
                uint32_t* p = &S[0][samp * SSTRIDE + 4 * f4];
                p[0] = cvt_tf32(vreg[l].x);
                p[1] = cvt_tf32(vreg[l].y);
                p[2] = cvt_tf32(vreg[l].z);
                p[3] = cvt_tf32(vreg[l].w);
            }
        }

        for (int s = 0; s < nblk; ++s) {
            __syncthreads();                 // S[s&1] ready; prior compute done
            if (s + 1 < nblk) {
                int s0 = sb + 16 * (s + 1);
                for (int l = 0; l < nit; ++l) {
                    int idx = tid + 256 * l;
                    int samp = idx / nf4, f4 = idx % nf4;
                    int si = s0 + samp;
                    int sp = (si < se) ? g_perm[si] : -1;
                    vreg[l] = (sp >= 0) ? X4[(size_t)sp * 64 + flo4 + f4]
                                        : make_float4(0.f, 0.f, 0.f, 0.f);
                }
            }
            const uint32_t* Sb = S[s & 1];
#pragma unroll
            for (int kb = 0; kb < 16; kb += 8) {
                int r0 = (kb + tig) * SSTRIDE;
                int r1 = (kb + tig + 4) * SSTRIDE;
                uint32_t a[2][4];
#pragma unroll
                for (int mf = 0; mf < 2; ++mf) {
                    int m0 = MbL + 16 * mf + gid;
                    a[mf][0] = Sb[r0 + m0];
                    a[mf][1] = Sb[r0 + m0 + 8];
                    a[mf][2] = Sb[r1 + m0];
                    a[mf][3] = Sb[r1 + m0 + 8];
                }
#pragma unroll
                for (int nb = 0; nb < 8; ++nb) {
                    int n0 = NbL + 8 * nb + gid;
                    uint32_t b0 = Sb[r0 + n0];
                    uint32_t b1 = Sb[r1 + n0];
                    mma_tf32(acc[0][nb], a[0], b0, b1);
                    mma_tf32(acc[1][nb], a[1], b0, b1);
                }
            }
            __syncthreads();                 // compute(s) done before refill
            if (s + 1 < nblk) {
                uint32_t* Sn = S[(s + 1) & 1];
                for (int l = 0; l < nit; ++l) {
                    int idx = tid + 256 * l;
                    int samp = idx / nf4, f4 = idx % nf4;
                    uint32_t* p = &Sn[samp * SSTRIDE + 4 * f4];
                    p[0] = cvt_tf32(vreg[l].x);
                    p[1] = cvt_tf32(vreg[l].y);
                    p[2] = cvt_tf32(vreg[l].z);
                    p[3] = cvt_tf32(vreg[l].w);
                }
            }
        }

        // epilogue: write this tile's 32x64 warp region to g_part
        float* op = g_part[(ch * KK + k) * NTILE + t];
#pragma unroll
        for (int mf = 0; mf < 2; ++mf) {
#pragma unroll
            for (int nb = 0; nb < 8; ++nb) {
                int row0 = MbL + 16 * mf + gid;
                int col = 64 * nw + 8 * nb + 2 * tig;
                *(float2*)&op[row0 * 128 + col] =
                    make_float2(acc[mf][nb][0], acc[mf][nb][1]);
                *(float2*)&op[(row0 + 8) * 128 + col] =
                    make_float2(acc[mf][nb][2], acc[mf][nb][3]);
            }
        }
        __syncthreads();                     // before next tile reuses S
    }
}

// ----------------- 6. reduce chunk partials -> full mirrored cov -----------------
__global__ void k_reduce() {
    int r = blockIdx.x;           // k*3 + t
    int k = r / NTILE, t = r % NTILE;
    int tid = threadIdx.x;
    for (int e = tid; e < 16384; e += 256) {
        float sum = 0.f;
#pragma unroll
        for (int ch = 0; ch < NCH; ++ch) sum += g_part[ch * (KK * NTILE) + r][e];
        int i = e >> 7, j = e & 127;
        if (t == 0)      g_cov[k][i * DD + j] = sum;
        else if (t == 2) g_cov[k][(128 + i) * DD + 128 + j] = sum;
        else {
            g_cov[k][i * DD + 128 + j] = sum;
            g_cov[k][(128 + j) * DD + i] = sum;
        }
    }
}

__global__ void k_gram() {
    int e = blockIdx.x * 256 + threadIdx.x;
    float s = 0.f;
#pragma unroll
    for (int k = 0; k < KK; ++k) s += g_cov[k][e];
    g_gram[e] = s;
}

// ----------------- 7. blocked Cholesky (packed lower tri in smem) + logdet -----------------
__global__ void k_chol() {
    extern __shared__ float Ls[];    // TRI_N floats = 131584 bytes
    __shared__ float sinv;
    __shared__ double red[256];

    int b = blockIdx.x;
    const float* A = (b == 0) ? g_gram : g_cov[b - 1];
    float s;
    if (b == 0) s = 256.0f / (65536.0f * 0.01f);
    else {
        double tr = (double)g_count[b - 1] + 1e-8;
        s = (float)(256.0 / (tr * 0.01));
    }
    int tid = threadIdx.x;

    // load I + s*A, packed lower triangle
    for (int p = tid; p < TRI_N; p += 256) {
        int i = (int)((sqrtf(8.f * (float)p + 1.f) - 1.f) * 0.5f);
        while (tri(i + 1) <= p) ++i;
        while (tri(i) > p) --i;
        int j = p - tri(i);
        Ls[p] = ((i == j) ? 1.f : 0.f) + s * A[i * DD + j];
    }
    __syncthreads();

    for (int j0 = 0; j0 < DD; j0 += 16) {
        // unblocked full-height panel factor, cols j0..j0+15
        for (int jj = 0; jj < 16; ++jj) {
            int j = j0 + jj;
            if (tid == 0) {
                float d = Ls[tri(j) + j];
                float rr = sqrtf(d);
                Ls[tri(j) + j] = rr;
                sinv = 1.f / rr;
            }
            __syncthreads();
            float iv = sinv;
            for (int i = j + 1 + tid; i < DD; i += 256) Ls[tri(i) + j] *= iv;
            __syncthreads();
            int cend = j0 + 16;
            for (int i = j + 1 + tid; i < DD; i += 256) {
                float lij = Ls[tri(i) + j];
                int cm = (i < cend - 1) ? i : cend - 1;
                for (int c = j + 1; c <= cm; ++c)
                    Ls[tri(i) + c] -= lij * Ls[tri(c) + j];
            }
            __syncthreads();
        }
        // rank-16 trailing update: warp-per-64-col block, broadcast panel rows,
        // f32x2 column-pair accumulators.
        {
            int w = tid >> 5, l = tid & 31;
            int cb = j0 + 16 + 64 * w;      // column block start
            int c = cb + 2 * l;             // this lane's column pair
            if (c < DD) {
                ull lcn[16];
                int tc0 = tri(c) + j0, tc1 = tri(c + 1) + j0;
#pragma unroll
                for (int q = 0; q < 16; ++q)
                    lcn[q] = pk2(-Ls[tc0 + q], -Ls[tc1 + q]);
                int cd = c - j0;
                for (int r = cb; r < DD; ++r) {
                    int base = tri(r) + j0;
                    bool a0 = (r >= c), a1 = (r > c);
                    float x0 = a0 ? Ls[base + cd] : 0.f;
                    float x1 = a1 ? Ls[base + cd + 1] : 0.f;
                    ull acc = pk2(x0, x1);
#pragma unroll
                    for (int q = 0; q < 16; ++q) {
                        float p = Ls[base + q];      // broadcast across warp
                        acc = ffma2(pk2(p, p), lcn[q], acc);
                    }
                    float2 res = upk2(acc);
                    if (a0) Ls[base + cd] = res.x;
                    if (a1) Ls[base + cd + 1] = res.y;
                }
            }
        }
        __syncthreads();
    }

    // logdet = 2 * sum(ln L_ii), fp64 tree reduce (deterministic)
    red[tid] = log((double)Ls[tri(tid) + tid]);
    __syncthreads();
    for (int st = 128; st > 0; st >>= 1) {
        if (tid < st) red[tid] += red[tid + st];
        __syncthreads();
    }
    if (tid == 0) g_logdet[b] = 2.0 * red[0];
}

// ----------------- 8. finalize -----------------
__global__ void k_final(float* out) {
    double disc = 0.5 * g_logdet[0];
    double comp = 0.0;
    for (int k = 0; k < KK; ++k) {
        double tr = (double)g_count[k] + 1e-8;
        comp += g_logdet[k + 1] * tr;
    }
    comp = comp / 65536.0 / 2.0;
    out[0] = (float)(-disc + comp);
    out[1] = (float)disc;
    out[2] = (float)comp;
    out[3] = (float)disc;
    out[4] = (float)comp;
}

// ----------------- host -----------------
extern "C" void kernel_launch(void* const* d_in, const int* in_sizes, int n_in,
                              void* d_out, int out_size) {
    const float* X = 0;
    const int* Y = 0;
    for (int i = 0; i < n_in; ++i) {
        if (in_sizes[i] == NS * DD) X = (const float*)d_in[i];
        else if (in_sizes[i] == NS) Y = (const int*)d_in[i];
    }
    if (!X) X = (const float*)d_in[0];
    if (!Y) Y = (const int*)d_in[1];
    float* out = (float*)d_out;

    k_detect<<<1, 256>>>(Y);
    k_hist<<<16, 256>>>(Y);
    k_scan<<<KK, 256>>>();
    k_offs<<<1, 32>>>();
    k_scat<<<16, 256>>>(Y);
    k_syrk_mma<<<NCH * KK, 256>>>(X);
    k_reduce<<<KK * NTILE, 256>>>();
    k_gram<<<256, 256>>>();
    cudaFuncSetAttribute(k_chol, cudaFuncAttributeMaxDynamicSharedMemorySize,
                         TRI_N * (int)sizeof(float));
    k_chol<<<KK + 1, 256, TRI_N * sizeof(float)>>>();
    k_final<<<1, 1>>>(out);
    (void)out_size;
}

// round 10
// speedup vs baseline: 1.3443x; 1.3443x over previous
#include <cuda_runtime.h>
#include <math.h>
#include <stdint.h>

#define NS   65536
#define DD   256
#define KK   10
#define NCH  14          // sample chunks per class -> 140 CTAs (one wave)
#define SORT_T 4096      // 16 blocks x 256 sorting threads
#define SPT  16          // samples per sorting thread
#define NTILE 3          // (0,0),(0,1),(1,1) 128x128 tiles of 256x256
#define TRI_N 32896      // 256*257/2
#define SSTRIDE 264      // smem sample stride in floats (256+8): bank-perfect

typedef unsigned long long ull;

// ----------------- device scratch (static globals; no allocation) -----------------
__device__ int    g_is64;
__device__ int    g_hist[KK * SORT_T];
__device__ int    g_count[KK];
__device__ int    g_off[KK];
__device__ int    g_perm[NS];
__device__ float  g_part[NCH * KK * NTILE][16384];   // ~27.5 MB partial tiles
__device__ float  g_cov[KK][DD * DD];
__device__ float  g_gram[DD * DD];
__device__ double g_logdet[KK + 1];                  // [0]=gram, [1..10]=classes

// ----------------- f32x2 helpers (packed fp32 FMA, plain sm_103-legal) -----------------
__device__ __forceinline__ ull pk2(float x, float y) {
    ull d;
    asm("mov.b64 %0, {%1, %2};" : "=l"(d)
        : "r"(__float_as_uint(x)), "r"(__float_as_uint(y)));
    return d;
}
__device__ __forceinline__ ull ffma2(ull a, ull b, ull c) {
    ull d;
    asm("fma.rn.f32x2 %0, %1, %2, %3;" : "=l"(d) : "l"(a), "l"(b), "l"(c));
    return d;
}
__device__ __forceinline__ float2 upk2(ull d) {
    unsigned int lo, hi;
    asm("mov.b64 {%0, %1}, %2;" : "=r"(lo), "=r"(hi) : "l"(d));
    return make_float2(__uint_as_float(lo), __uint_as_float(hi));
}

__device__ __forceinline__ int tri(int i) { return (i * (i + 1)) >> 1; }

__device__ __forceinline__ uint32_t cvt_tf32(float f) {
    uint32_t r;
    asm("cvt.rna.tf32.f32 %0, %1;" : "=r"(r) : "f"(f));
    return r;
}
__device__ __forceinline__ void mma_tf32(float d[4], const uint32_t a[4],
                                         uint32_t b0, uint32_t b1) {
    asm volatile(
        "mma.sync.aligned.m16n8k8.row.col.f32.tf32.tf32.f32 "
        "{%0,%1,%2,%3}, {%4,%5,%6,%7}, {%8,%9}, {%0,%1,%2,%3};"
        : "+f"(d[0]), "+f"(d[1]), "+f"(d[2]), "+f"(d[3])
        : "r"(a[0]), "r"(a[1]), "r"(a[2]), "r"(a[3]), "r"(b0), "r"(b1));
}

// ----------------- 0. label dtype detection (int64 vs int32) -----------------
__global__ void k_detect(const int* __restrict__ Y) {
    __shared__ int bad;
    if (threadIdx.x == 0) bad = 0;
    __syncthreads();
    int viol = 0;
    for (int w = 0; w < 8; ++w) {
        int idx = threadIdx.x * 8 + w;
        int v = Y[idx];
        if (idx & 1) { if (v != 0) viol = 1; }
        else         { if (v < 0 || v >= KK) viol = 1; }
    }
    if (viol) atomicOr(&bad, 1);
    __syncthreads();
    if (threadIdx.x == 0) g_is64 = bad ? 0 : 1;
}

// ----------------- 1-3. deterministic stable counting sort of labels -----------------
__global__ void k_hist(const int* __restrict__ Y) {
    int t = blockIdx.x * blockDim.x + threadIdx.x;
    int cnt[KK];
#pragma unroll
    for (int c = 0; c < KK; ++c) cnt[c] = 0;
    int is64 = g_is64;
    int base = t * SPT;
    for (int q = 0; q < SPT; ++q) {
        int i = base + q;
        int lab = is64 ? Y[2 * i] : Y[i];
        cnt[lab]++;
    }
#pragma unroll
    for (int c = 0; c < KK; ++c) g_hist[c * SORT_T + t] = cnt[c];
}

__global__ void k_scan() {
    int c = blockIdx.x, tid = threadIdx.x;
    int* h = g_hist + c * SORT_T;
    int loc[16];
    int base = tid * 16;
    int tsum = 0;
#pragma unroll
    for (int q = 0; q < 16; ++q) { loc[q] = h[base + q]; tsum += loc[q]; }
    __shared__ int sh[256];
    sh[tid] = tsum;
    __syncthreads();
    for (int st = 1; st < 256; st <<= 1) {
        int v = 0;
        if (tid >= st) v = sh[tid - st];
        __syncthreads();
        if (tid >= st) sh[tid] += v;
        __syncthreads();
    }
    int run = sh[tid] - tsum;
#pragma unroll
    for (int q = 0; q < 16; ++q) { h[base + q] = run; run += loc[q]; }
    if (tid == 255) g_count[c] = sh[255];
}

// scatter; also computes class offsets (folded former k_offs)
__global__ void k_scat(const int* __restrict__ Y) {
    __shared__ int soff[KK];
    if (threadIdx.x < KK) {
        int a = 0;
        for (int c = 0; c < (int)threadIdx.x; ++c) a += g_count[c];
        soff[threadIdx.x] = a;
        if (blockIdx.x == 0) g_off[threadIdx.x] = a;   // for later kernels
    }
    __syncthreads();
    int t = blockIdx.x * blockDim.x + threadIdx.x;
    int cnt[KK];
#pragma unroll
    for (int c = 0; c < KK; ++c) cnt[c] = 0;
    int is64 = g_is64;
    int base = t * SPT;
    for (int q = 0; q < SPT; ++q) {
        int i = base + q;
        int lab = is64 ? Y[2 * i] : Y[i];
        int pos = soff[lab] + g_hist[lab * SORT_T + t] + cnt[lab];
        cnt[lab]++;
        g_perm[pos] = i;
    }
}

// ----------------- 5. grouped SYRK via mma.sync tf32 -----------------
// Templated per tile so all loader bounds are constexpr -> vreg stays in regs.
// NF4 = float4s per sample row loaded (32 or 64); FLO4 = float4 offset in X row.
template<int NF4, int FLO4>
__device__ __forceinline__ void syrk_tile(
    const float4* __restrict__ X4, int sb, int se, int nblk,
    uint32_t (*S)[16 * SSTRIDE], int tid, int MbL, int NbL, int ncol,
    float* __restrict__ op, int gid, int tig)
{
    constexpr int NIT = NF4 / 16;     // float4s per thread per 16-sample block

    float acc[2][8][4];
#pragma unroll
    for (int a = 0; a < 2; ++a)
#pragma unroll
        for (int n = 0; n < 8; ++n)
#pragma unroll
            for (int c = 0; c < 4; ++c) acc[a][n][c] = 0.f;

    float4 vreg[NIT];

    auto ld = [&](int s0) {
#pragma unroll
        for (int l = 0; l < NIT; ++l) {
            int idx = tid + 256 * l;
            int samp = idx / NF4, f4 = idx % NF4;
            int si = s0 + samp;
            int sp = (si < se) ? g_perm[si] : -1;
            vreg[l] = (sp >= 0) ? X4[(size_t)sp * 64 + FLO4 + f4]
                                : make_float4(0.f, 0.f, 0.f, 0.f);
        }
    };
    auto st = [&](uint32_t* Sn) {
#pragma unroll
        for (int l = 0; l < NIT; ++l) {
            int idx = tid + 256 * l;
            int samp = idx / NF4, f4 = idx % NF4;
            uint32_t* p = &Sn[samp * SSTRIDE + 4 * f4];
            p[0] = cvt_tf32(vreg[l].x);
            p[1] = cvt_tf32(vreg[l].y);
            p[2] = cvt_tf32(vreg[l].z);
            p[3] = cvt_tf32(vreg[l].w);
        }
    };

    if (nblk > 0) { ld(sb); st(S[0]); }

    for (int s = 0; s < nblk; ++s) {
        __syncthreads();                  // S[s&1] ready; prior compute done
        if (s + 1 < nblk) ld(sb + 16 * (s + 1));
        const uint32_t* Sb = S[s & 1];
#pragma unroll
        for (int kb = 0; kb < 16; kb += 8) {
            int r0 = (kb + tig) * SSTRIDE;
            int r1 = (kb + tig + 4) * SSTRIDE;
            uint32_t a[2][4];
#pragma unroll
            for (int mf = 0; mf < 2; ++mf) {
                int m0 = MbL + 16 * mf + gid;
                a[mf][0] = Sb[r0 + m0];
                a[mf][1] = Sb[r0 + m0 + 8];
                a[mf][2] = Sb[r1 + m0];
                a[mf][3] = Sb[r1 + m0 + 8];
            }
#pragma unroll
            for (int nb = 0; nb < 8; ++nb) {
                int n0 = NbL + 8 * nb + gid;
                uint32_t b0 = Sb[r0 + n0];
                uint32_t b1 = Sb[r1 + n0];
                mma_tf32(acc[0][nb], a[0], b0, b1);
                mma_tf32(acc[1][nb], a[1], b0, b1);
            }
        }
        __syncthreads();                  // compute(s) done before refill
        if (s + 1 < nblk) st(S[(s + 1) & 1]);
    }

    // epilogue: 32x64 warp region
#pragma unroll
    for (int mf = 0; mf < 2; ++mf) {
#pragma unroll
        for (int nb = 0; nb < 8; ++nb) {
            int row0 = MbL + 16 * mf + gid;
            int col = ncol + 8 * nb + 2 * tig;
            *(float2*)&op[row0 * 128 + col] =
                make_float2(acc[mf][nb][0], acc[mf][nb][1]);
            *(float2*)&op[(row0 + 8) * 128 + col] =
                make_float2(acc[mf][nb][2], acc[mf][nb][3]);
        }
    }
    __syncthreads();                      // before S reuse by next tile
}

__global__ void __launch_bounds__(256, 1) k_syrk_mma(const float* __restrict__ X) {
    __shared__ uint32_t S[2][16 * SSTRIDE];

    int tid = threadIdx.x, wid = tid >> 5, lane = tid & 31;
    int gid = lane >> 2, tig = lane & 3;

    int b = blockIdx.x;
    int ch = b / KK, k = b % KK;
    int off = g_off[k], cnt = g_count[k];
    int len = (cnt + NCH - 1) / NCH;
    int sb = off + ch * len;
    int se = off + cnt;
    if (sb + len < se) se = sb + len;
    int nblk = (se > sb) ? (se - sb + 15) / 16 : 0;

    const float4* X4 = (const float4*)X;
    int mw = wid >> 1, nw = wid & 1;       // 4 x 2 warp grid
    int MbL = 32 * mw, ncol = 64 * nw;
    float* base_op = g_part[(ch * KK + k) * NTILE];

    syrk_tile<32, 0>(X4, sb, se, nblk, S, tid, MbL, ncol, ncol,
                     base_op, gid, tig);
    syrk_tile<64, 0>(X4, sb, se, nblk, S, tid, MbL, 128 + ncol, ncol,
                     base_op + 16384, gid, tig);
    syrk_tile<32, 32>(X4, sb, se, nblk, S, tid, MbL, ncol, ncol,
                     base_op + 32768, gid, tig);
}

// ----------------- 6. reduce chunk partials -> full mirrored cov -----------------
__global__ void k_reduce() {
    int blk = blockIdx.x;              // KK*NTILE*4 blocks
    int r = blk >> 2, quad = blk & 3;
    int k = r / NTILE, t = r % NTILE;
    int tid = threadIdx.x;
    int e0 = quad * 4096;
    for (int e = e0 + tid; e < e0 + 4096; e += 256) {
        float sum = 0.f;
#pragma unroll
        for (int ch = 0; ch < NCH; ++ch) sum += g_part[ch * (KK * NTILE) + r][e];
        int i = e >> 7, j = e & 127;
        if (t == 0)      g_cov[k][i * DD + j] = sum;
        else if (t == 2) g_cov[k][(128 + i) * DD + 128 + j] = sum;
        else {
            g_cov[k][i * DD + 128 + j] = sum;
            g_cov[k][(128 + j) * DD + i] = sum;
        }
    }
}

__global__ void k_gram() {
    int e = blockIdx.x * 256 + threadIdx.x;
    float s = 0.f;
#pragma unroll
    for (int k = 0; k < KK; ++k) s += g_cov[k][e];
    g_gram[e] = s;
}

// ----------------- 7. blocked Cholesky (packed lower tri in smem) + logdet -----------------
__global__ void k_chol() {
    extern __shared__ float Ls[];    // TRI_N floats = 131584 bytes
    __shared__ float sinv;
    __shared__ double red[256];

    int b = blockIdx.x;
    const float* A = (b == 0) ? g_gram : g_cov[b - 1];
    float s;
    if (b == 0) s = 256.0f / (65536.0f * 0.01f);
    else {
        double tr = (double)g_count[b - 1] + 1e-8;
        s = (float)(256.0 / (tr * 0.01));
    }
    int tid = threadIdx.x;

    // load I + s*A, packed lower triangle
    for (int p = tid; p < TRI_N; p += 256) {
        int i = (int)((sqrtf(8.f * (float)p + 1.f) - 1.f) * 0.5f);
        while (tri(i + 1) <= p) ++i;
        while (tri(i) > p) --i;
        int j = p - tri(i);
        Ls[p] = ((i == j) ? 1.f : 0.f) + s * A[i * DD + j];
    }
    __syncthreads();

    for (int j0 = 0; j0 < DD; j0 += 16) {
        // unblocked full-height panel factor, cols j0..j0+15
        for (int jj = 0; jj < 16; ++jj) {
            int j = j0 + jj;
            if (tid == 0) {
                float d = Ls[tri(j) + j];
                float rr = sqrtf(d);
                Ls[tri(j) + j] = rr;
                sinv = 1.f / rr;
            }
            __syncthreads();
            float iv = sinv;
            for (int i = j + 1 + tid; i < DD; i += 256) Ls[tri(i) + j] *= iv;
            __syncthreads();
            int cend = j0 + 16;
            for (int i = j + 1 + tid; i < DD; i += 256) {
                float lij = Ls[tri(i) + j];
                int cm = (i < cend - 1) ? i : cend - 1;
                for (int c = j + 1; c <= cm; ++c)
                    Ls[tri(i) + c] -= lij * Ls[tri(c) + j];
            }
            __syncthreads();
        }
        // rank-16 trailing update: 2 warps per 64-col block (interleaved 4-row
        // groups), f32x2 col-pair accumulators, ILP-4 rows to hide FMA latency.
        {
            int w = tid >> 5, l = tid & 31;
            int v = w >> 1, ph = w & 1;
            int cb = j0 + 16 + 64 * v;
            int c = cb + 2 * l;
            if (c < DD) {
                ull lcn[16];
                int tc0 = tri(c) + j0, tc1 = tri(c + 1) + j0;
#pragma unroll
                for (int q = 0; q < 16; ++q)
                    lcn[q] = pk2(-Ls[tc0 + q], -Ls[tc1 + q]);
                int cd = c - j0;
                for (int r0 = cb + 4 * ph; r0 < DD; r0 += 8) {
                    int base[4]; ull acc[4]; bool a0[4], a1[4];
#pragma unroll
                    for (int u = 0; u < 4; ++u) {
                        int r = r0 + u;
                        base[u] = tri(r) + j0;
                        a0[u] = (r >= c); a1[u] = (r > c);
                        float x0 = a0[u] ? Ls[base[u] + cd] : 0.f;
                        float x1 = a1[u] ? Ls[base[u] + cd + 1] : 0.f;
                        acc[u] = pk2(x0, x1);
                    }
#pragma unroll
                    for (int q = 0; q < 16; ++q) {
#pragma unroll
                        for (int u = 0; u < 4; ++u) {
                            float p = Ls[base[u] + q];   // broadcast across warp
                            acc[u] = ffma2(pk2(p, p), lcn[q], acc[u]);
                        }
                    }
#pragma unroll
                    for (int u = 0; u < 4; ++u) {
                        float2 res = upk2(acc[u]);
                        if (a0[u]) Ls[base[u] + cd] = res.x;
                        if (a1[u]) Ls[base[u] + cd + 1] = res.y;
                    }
                }
            }
        }
        __syncthreads();
    }

    // logdet = 2 * sum(ln L_ii), fp64 tree reduce (deterministic)
    red[tid] = log((double)Ls[tri(tid) + tid]);
    __syncthreads();
    for (int st = 128; st > 0; st >>= 1) {
        if (tid < st) red[tid] += red[tid + st];
        __syncthreads();
    }
    if (tid == 0) g_logdet[b] = 2.0 * red[0];
}

// ----------------- 8. finalize -----------------
__global__ void k_final(float* out) {
    double disc = 0.5 * g_logdet[0];
    double comp = 0.0;
    for (int k = 0; k < KK; ++k) {
        double tr = (double)g_count[k] + 1e-8;
        comp += g_logdet[k + 1] * tr;
    }
    comp = comp / 65536.0 / 2.0;
    out[0] = (float)(-disc + comp);
    out[1] = (float)disc;
    out[2] = (float)comp;
    out[3] = (float)disc;
    out[4] = (float)comp;
}

// ----------------- host -----------------
extern "C" void kernel_launch(void* const* d_in, const int* in_sizes, int n_in,
                              void* d_out, int out_size) {
    const float* X = 0;
    const int* Y = 0;
    for (int i = 0; i < n_in; ++i) {
        if (in_sizes[i] == NS * DD) X = (const float*)d_in[i];
        else if (in_sizes[i] == NS) Y = (const int*)d_in[i];
    }
    if (!X) X = (const float*)d_in[0];
    if (!Y) Y = (const int*)d_in[1];
    float* out = (float*)d_out;

    k_detect<<<1, 256>>>(Y);
    k_hist<<<16, 256>>>(Y);
    k_scan<<<KK, 256>>>();
    k_scat<<<16, 256>>>(Y);
    k_syrk_mma<<<NCH * KK, 256>>>(X);
    k_reduce<<<KK * NTILE * 4, 256>>>();
    k_gram<<<256, 256>>>();
    cudaFuncSetAttribute(k_chol, cudaFuncAttributeMaxDynamicSharedMemorySize,
                         TRI_N * (int)sizeof(float));
    k_chol<<<KK + 1, 256, TRI_N * sizeof(float)>>>();
    k_final<<<1, 1>>>(out);
    (void)out_size;
}

// round 11
// speedup vs baseline: 1.9105x; 1.4212x over previous
#include <cuda_runtime.h>
#include <math.h>
#include <stdint.h>

#define NS   65536
#define DD   256
#define KK   10
#define NCH  14          // sample chunks per class -> 140 CTAs (one wave)
#define SORT_T 4096      // 16 blocks x 256 sorting threads
#define SPT  16          // samples per sorting thread
#define NTILE 3          // (0,0),(0,1),(1,1) 128x128 tiles of 256x256
#define TRI_N 32896      // 256*257/2
#define SSTRIDE 264      // smem sample stride in floats (256+8): bank-perfect

typedef unsigned long long ull;

// ----------------- device scratch (static globals; no allocation) -----------------
__device__ int    g_hist[KK * SORT_T];
__device__ int    g_count[KK];
__device__ int    g_off[KK];
__device__ int    g_perm[NS];
__device__ float  g_part[NCH * KK * NTILE][16384];   // ~27.5 MB partial tiles
__device__ float  g_cov[KK][DD * DD];
__device__ float  g_gram[DD * DD];
__device__ double g_logdet[KK + 1];                  // [0]=gram, [1..10]=classes

// ----------------- f32x2 helpers (packed fp32 FMA, plain sm_103-legal) -----------------
__device__ __forceinline__ ull pk2(float x, float y) {
    ull d;
    asm("mov.b64 %0, {%1, %2};" : "=l"(d)
        : "r"(__float_as_uint(x)), "r"(__float_as_uint(y)));
    return d;
}
__device__ __forceinline__ ull ffma2(ull a, ull b, ull c) {
    ull d;
    asm("fma.rn.f32x2 %0, %1, %2, %3;" : "=l"(d) : "l"(a), "l"(b), "l"(c));
    return d;
}
__device__ __forceinline__ float2 upk2(ull d) {
    unsigned int lo, hi;
    asm("mov.b64 {%0, %1}, %2;" : "=r"(lo), "=r"(hi) : "l"(d));
    return make_float2(__uint_as_float(lo), __uint_as_float(hi));
}

__device__ __forceinline__ int tri(int i) { return (i * (i + 1)) >> 1; }

__device__ __forceinline__ uint32_t cvt_tf32(float f) {
    uint32_t r;
    asm("cvt.rna.tf32.f32 %0, %1;" : "=r"(r) : "f"(f));
    return r;
}
__device__ __forceinline__ void mma_tf32(float d[4], const uint32_t a[4],
                                         uint32_t b0, uint32_t b1) {
    asm volatile(
        "mma.sync.aligned.m16n8k8.row.col.f32.tf32.tf32.f32 "
        "{%0,%1,%2,%3}, {%4,%5,%6,%7}, {%8,%9}, {%0,%1,%2,%3};"
        : "+f"(d[0]), "+f"(d[1]), "+f"(d[2]), "+f"(d[3])
        : "r"(a[0]), "r"(a[1]), "r"(a[2]), "r"(a[3]), "r"(b0), "r"(b1));
}

// Block-local int64-vs-int32 label detection (deterministic; every block
// derives the same answer from the first 2048 32-bit words of Y).
__device__ __forceinline__ int detect_is64_block(const int* __restrict__ Y,
                                                 int* sh_bad) {
    if (threadIdx.x == 0) *sh_bad = 0;
    __syncthreads();
    int viol = 0;
#pragma unroll
    for (int w = 0; w < 8; ++w) {
        int idx = (int)threadIdx.x * 8 + w;
        int v = Y[idx];
        if (idx & 1) { if (v != 0) viol = 1; }
        else         { if (v < 0 || v >= KK) viol = 1; }
    }
    if (viol) atomicOr(sh_bad, 1);
    __syncthreads();
    return (*sh_bad) ? 0 : 1;
}

// ----------------- 1-3. deterministic stable counting sort of labels -----------------
__global__ void k_hist(const int* __restrict__ Y) {
    __shared__ int sh_bad;
    int is64 = detect_is64_block(Y, &sh_bad);
    int t = blockIdx.x * blockDim.x + threadIdx.x;
    int cnt[KK];
#pragma unroll
    for (int c = 0; c < KK; ++c) cnt[c] = 0;
    int base = t * SPT;
    for (int q = 0; q < SPT; ++q) {
        int i = base + q;
        int lab = is64 ? Y[2 * i] : Y[i];
        cnt[lab]++;
    }
#pragma unroll
    for (int c = 0; c < KK; ++c) g_hist[c * SORT_T + t] = cnt[c];
}

__global__ void k_scan() {
    int c = blockIdx.x, tid = threadIdx.x;
    int* h = g_hist + c * SORT_T;
    int loc[16];
    int base = tid * 16;
    int tsum = 0;
#pragma unroll
    for (int q = 0; q < 16; ++q) { loc[q] = h[base + q]; tsum += loc[q]; }
    __shared__ int sh[256];
    sh[tid] = tsum;
    __syncthreads();
    for (int st = 1; st < 256; st <<= 1) {
        int v = 0;
        if (tid >= st) v = sh[tid - st];
        __syncthreads();
        if (tid >= st) sh[tid] += v;
        __syncthreads();
    }
    int run = sh[tid] - tsum;
#pragma unroll
    for (int q = 0; q < 16; ++q) { h[base + q] = run; run += loc[q]; }
    if (tid == 255) g_count[c] = sh[255];
}

// scatter; also publishes class offsets
__global__ void k_scat(const int* __restrict__ Y) {
    __shared__ int sh_bad;
    __shared__ int soff[KK];
    int is64 = detect_is64_block(Y, &sh_bad);
    if (threadIdx.x < KK) {
        int a = 0;
        for (int c = 0; c < (int)threadIdx.x; ++c) a += g_count[c];
        soff[threadIdx.x] = a;
        if (blockIdx.x == 0) g_off[threadIdx.x] = a;
    }
    __syncthreads();
    int t = blockIdx.x * blockDim.x + threadIdx.x;
    int cnt[KK];
#pragma unroll
    for (int c = 0; c < KK; ++c) cnt[c] = 0;
    int base = t * SPT;
    for (int q = 0; q < SPT; ++q) {
        int i = base + q;
        int lab = is64 ? Y[2 * i] : Y[i];
        int pos = soff[lab] + g_hist[lab * SORT_T + t] + cnt[lab];
        cnt[lab]++;
        g_perm[pos] = i;
    }
}

// ----------------- 4. grouped SYRK via mma.sync tf32 -----------------
// Templated per tile so all loader bounds are constexpr -> vreg stays in regs.
template<int NF4, int FLO4>
__device__ __forceinline__ void syrk_tile(
    const float4* __restrict__ X4, int sb, int se, int nblk,
    uint32_t (*S)[16 * SSTRIDE], int tid, int MbL, int NbL, int ncol,
    float* __restrict__ op, int gid, int tig)
{
    constexpr int NIT = NF4 / 16;     // float4s per thread per 16-sample block

    float acc[2][8][4];
#pragma unroll
    for (int a = 0; a < 2; ++a)
#pragma unroll
        for (int n = 0; n < 8; ++n)
#pragma unroll
            for (int c = 0; c < 4; ++c) acc[a][n][c] = 0.f;

    float4 vreg[NIT];

    auto ld = [&](int s0) {
#pragma unroll
        for (int l = 0; l < NIT; ++l) {
            int idx = tid + 256 * l;
            int samp = idx / NF4, f4 = idx % NF4;
            int si = s0 + samp;
            int sp = (si < se) ? g_perm[si] : -1;
            vreg[l] = (sp >= 0) ? X4[(size_t)sp * 64 + FLO4 + f4]
                                : make_float4(0.f, 0.f, 0.f, 0.f);
        }
    };
    auto st = [&](uint32_t* Sn) {
#pragma unroll
        for (int l = 0; l < NIT; ++l) {
            int idx = tid + 256 * l;
            int samp = idx / NF4, f4 = idx % NF4;
            uint32_t* p = &Sn[samp * SSTRIDE + 4 * f4];
            p[0] = cvt_tf32(vreg[l].x);
            p[1] = cvt_tf32(vreg[l].y);
            p[2] = cvt_tf32(vreg[l].z);
            p[3] = cvt_tf32(vreg[l].w);
        }
    };

    if (nblk > 0) { ld(sb); st(S[0]); }

    for (int s = 0; s < nblk; ++s) {
        __syncthreads();                  // S[s&1] ready; prior compute done
        if (s + 1 < nblk) ld(sb + 16 * (s + 1));
        const uint32_t* Sb = S[s & 1];
#pragma unroll
        for (int kb = 0; kb < 16; kb += 8) {
            int r0 = (kb + tig) * SSTRIDE;
            int r1 = (kb + tig + 4) * SSTRIDE;
            uint32_t a[2][4];
#pragma unroll
            for (int mf = 0; mf < 2; ++mf) {
                int m0 = MbL + 16 * mf + gid;
                a[mf][0] = Sb[r0 + m0];
                a[mf][1] = Sb[r0 + m0 + 8];
                a[mf][2] = Sb[r1 + m0];
                a[mf][3] = Sb[r1 + m0 + 8];
            }
#pragma unroll
            for (int nb = 0; nb < 8; ++nb) {
                int n0 = NbL + 8 * nb + gid;
                uint32_t b0 = Sb[r0 + n0];
                uint32_t b1 = Sb[r1 + n0];
                mma_tf32(acc[0][nb], a[0], b0, b1);
                mma_tf32(acc[1][nb], a[1], b0, b1);
            }
        }
        __syncthreads();                  // compute(s) done before refill
        if (s + 1 < nblk) st(S[(s + 1) & 1]);
    }

    // epilogue: 32x64 warp region
#pragma unroll
    for (int mf = 0; mf < 2; ++mf) {
#pragma unroll
        for (int nb = 0; nb < 8; ++nb) {
            int row0 = MbL + 16 * mf + gid;
            int col = ncol + 8 * nb + 2 * tig;
            *(float2*)&op[row0 * 128 + col] =
                make_float2(acc[mf][nb][0], acc[mf][nb][1]);
            *(float2*)&op[(row0 + 8) * 128 + col] =
                make_float2(acc[mf][nb][2], acc[mf][nb][3]);
        }
    }
    __syncthreads();                      // before S reuse by next tile
}

__global__ void __launch_bounds__(256, 1) k_syrk_mma(const float* __restrict__ X) {
    __shared__ uint32_t S[2][16 * SSTRIDE];

    int tid = threadIdx.x, wid = tid >> 5, lane = tid & 31;
    int gid = lane >> 2, tig = lane & 3;

    int b = blockIdx.x;
    int ch = b / KK, k = b % KK;
    int off = g_off[k], cnt = g_count[k];
    int len = (cnt + NCH - 1) / NCH;
    int sb = off + ch * len;
    int se = off + cnt;
    if (sb + len < se) se = sb + len;
    int nblk = (se > sb) ? (se - sb + 15) / 16 : 0;

    const float4* X4 = (const float4*)X;
    int mw = wid >> 1, nw = wid & 1;       // 4 x 2 warp grid
    int MbL = 32 * mw, ncol = 64 * nw;
    float* base_op = g_part[(ch * KK + k) * NTILE];

    syrk_tile<32, 0>(X4, sb, se, nblk, S, tid, MbL, ncol, ncol,
                     base_op, gid, tig);
    syrk_tile<64, 0>(X4, sb, se, nblk, S, tid, MbL, 128 + ncol, ncol,
                     base_op + 16384, gid, tig);
    syrk_tile<32, 32>(X4, sb, se, nblk, S, tid, MbL, ncol, ncol,
                     base_op + 32768, gid, tig);
}

// ----------------- 5. reduce chunk partials -> full mirrored cov -----------------
__global__ void k_reduce() {
    int blk = blockIdx.x;              // KK*NTILE*4 blocks
    int r = blk >> 2, quad = blk & 3;
    int k = r / NTILE, t = r % NTILE;
    int tid = threadIdx.x;
    int e0 = quad * 4096;
    for (int e = e0 + tid; e < e0 + 4096; e += 256) {
        float sum = 0.f;
#pragma unroll
        for (int ch = 0; ch < NCH; ++ch) sum += g_part[ch * (KK * NTILE) + r][e];
        int i = e >> 7, j = e & 127;
        if (t == 0)      g_cov[k][i * DD + j] = sum;
        else if (t == 2) g_cov[k][(128 + i) * DD + 128 + j] = sum;
        else {
            g_cov[k][i * DD + 128 + j] = sum;
            g_cov[k][(128 + j) * DD + i] = sum;
        }
    }
}

__global__ void k_gram() {
    int e = blockIdx.x * 256 + threadIdx.x;
    float s = 0.f;
#pragma unroll
    for (int k = 0; k < KK; ++k) s += g_cov[k][e];
    g_gram[e] = s;
}

// ----------------- 6. blocked right-looking Cholesky + logdet (512 thr) ----------
// Panel = 16 cols. Per panel: (A) warp-0 register factor of 16x16 diag block via
// shuffles (no block bars), (B) barrier-free row-parallel TRSM of the sub-panel,
// (C) rank-16 trailing update over 16 warps (f32x2, ILP-4). ~4 bars per panel.
__global__ void __launch_bounds__(512, 1) k_chol() {
    extern __shared__ float Ls[];    // TRI_N floats = 131584 bytes
    __shared__ float L11[16 * 16];
    __shared__ float inv11[16];
    __shared__ double red[512];

    int b = blockIdx.x;
    const float* A = (b == 0) ? g_gram : g_cov[b - 1];
    float s;
    if (b == 0) s = 256.0f / (65536.0f * 0.01f);
    else {
        double tr = (double)g_count[b - 1] + 1e-8;
        s = (float)(256.0 / (tr * 0.01));
    }
    int tid = threadIdx.x;
    int wid = tid >> 5, lane = tid & 31;

    // load I + s*A, packed lower triangle
    for (int p = tid; p < TRI_N; p += 512) {
        int i = (int)((sqrtf(8.f * (float)p + 1.f) - 1.f) * 0.5f);
        while (tri(i + 1) <= p) ++i;
        while (tri(i) > p) --i;
        int j = p - tri(i);
        Ls[p] = ((i == j) ? 1.f : 0.f) + s * A[i * DD + j];
    }
    __syncthreads();

    for (int j0 = 0; j0 < DD; j0 += 16) {
        // --- (A) diagonal block factor: warp 0, registers + shuffles ---
        if (wid == 0) {
            float x[16];
            int r = j0 + lane;
            if (lane < 16) {
#pragma unroll
                for (int q = 0; q < 16; ++q)
                    x[q] = (q <= lane) ? Ls[tri(r) + j0 + q] : 0.f;
            } else {
#pragma unroll
                for (int q = 0; q < 16; ++q) x[q] = 1.f;   // inert lanes
            }
#pragma unroll
            for (int c = 0; c < 16; ++c) {
                float piv = sqrtf(__shfl_sync(0xffffffffu, x[c], c));
                float iv = 1.f / piv;
                if (lane == c) x[c] = piv;
                else if (lane > c) x[c] *= iv;
#pragma unroll
                for (int q = c + 1; q < 16; ++q) {
                    float lqc = __shfl_sync(0xffffffffu, x[c], q);
                    if (lane >= q) x[q] -= x[c] * lqc;
                }
            }
            if (lane < 16) {
#pragma unroll
                for (int q = 0; q < 16; ++q)
                    if (q <= lane) {
                        Ls[tri(r) + j0 + q] = x[q];
                        L11[lane * 16 + q] = x[q];
                    }
                inv11[lane] = 1.f / x[lane];
            }
        }
        __syncthreads();

        // --- (B) TRSM: rows below panel, one row per thread, no bars inside ---
        for (int i = j0 + 16 + tid; i < DD; i += 512) {
            int base = tri(i) + j0;
            float x[16];
#pragma unroll
            for (int q = 0; q < 16; ++q) x[q] = Ls[base + q];
#pragma unroll
            for (int c = 0; c < 16; ++c) {
                float acc = x[c];
#pragma unroll
                for (int q = 0; q < c; ++q) acc -= L11[c * 16 + q] * x[q];
                x[c] = acc * inv11[c];
            }
#pragma unroll
            for (int q = 0; q < 16; ++q) Ls[base + q] = x[q];
        }
        __syncthreads();

        // --- (C) rank-16 trailing update: 4 warps per 64-col block ---
        {
            int v = wid >> 2, ph = wid & 3;
            int cb = j0 + 16 + 64 * v;
            int c = cb + 2 * lane;
            if (c < DD) {
                ull lcn[16];
                int tc0 = tri(c) + j0, tc1 = tri(c + 1) + j0;
#pragma unroll
                for (int q = 0; q < 16; ++q)
                    lcn[q] = pk2(-Ls[tc0 + q], -Ls[tc1 + q]);
                int cd = c - j0;
                for (int r0 = cb + 4 * ph; r0 < DD; r0 += 16) {
                    int base[4]; ull acc[4]; bool a0[4], a1[4];
#pragma unroll
                    for (int u = 0; u < 4; ++u) {
                        int r = r0 + u;
                        base[u] = tri(r) + j0;
                        a0[u] = (r >= c); a1[u] = (r > c);
                        float x0 = a0[u] ? Ls[base[u] + cd] : 0.f;
                        float x1 = a1[u] ? Ls[base[u] + cd + 1] : 0.f;
                        acc[u] = pk2(x0, x1);
                    }
#pragma unroll
                    for (int q = 0; q < 16; ++q) {
#pragma unroll
                        for (int u = 0; u < 4; ++u) {
                            float p = Ls[base[u] + q];   // broadcast across warp
                            acc[u] = ffma2(pk2(p, p), lcn[q], acc[u]);
                        }
                    }
#pragma unroll
                    for (int u = 0; u < 4; ++u) {
                        float2 res = upk2(acc[u]);
                        if (a0[u]) Ls[base[u] + cd] = res.x;
                        if (a1[u]) Ls[base[u] + cd + 1] = res.y;
                    }
                }
            }
        }
        __syncthreads();
    }

    // logdet = 2 * sum(ln L_ii), fp64 tree reduce (deterministic)
    red[tid] = (tid < DD) ? log((double)Ls[tri(tid) + tid]) : 0.0;
    __syncthreads();
    for (int st = 256; st > 0; st >>= 1) {
        if (tid < st) red[tid] += red[tid + st];
        __syncthreads();
    }
    if (tid == 0) g_logdet[b] = 2.0 * red[0];
}

// ----------------- 7. finalize -----------------
__global__ void k_final(float* out) {
    double disc = 0.5 * g_logdet[0];
    double comp = 0.0;
    for (int k = 0; k < KK; ++k) {
        double tr = (double)g_count[k] + 1e-8;
        comp += g_logdet[k + 1] * tr;
    }
    comp = comp / 65536.0 / 2.0;
    out[0] = (float)(-disc + comp);
    out[1] = (float)disc;
    out[2] = (float)comp;
    out[3] = (float)disc;
    out[4] = (float)comp;
}

// ----------------- host -----------------
extern "C" void kernel_launch(void* const* d_in, const int* in_sizes, int n_in,
                              void* d_out, int out_size) {
    const float* X = 0;
    const int* Y = 0;
    for (int i = 0; i < n_in; ++i) {
        if (in_sizes[i] == NS * DD) X = (const float*)d_in[i];
        else if (in_sizes[i] == NS) Y = (const int*)d_in[i];
    }
    if (!X) X = (const float*)d_in[0];
    if (!Y) Y = (const int*)d_in[1];
    float* out = (float*)d_out;

    k_hist<<<16, 256>>>(Y);
    k_scan<<<KK, 256>>>();
    k_scat<<<16, 256>>>(Y);
    k_syrk_mma<<<NCH * KK, 256>>>(X);     // launch idx 3 -> ncu captures this
    k_reduce<<<KK * NTILE * 4, 256>>>();
    k_gram<<<256, 256>>>();
    cudaFuncSetAttribute(k_chol, cudaFuncAttributeMaxDynamicSharedMemorySize,
                         TRI_N * (int)sizeof(float));
    k_chol<<<KK + 1, 512, TRI_N * sizeof(float)>>>();
    k_final<<<1, 1>>>(out);
    (void)out_size;
}

// round 13
// speedup vs baseline: 2.0740x; 1.0856x over previous
#include <cuda_runtime.h>
#include <math.h>
#include <stdint.h>

#define NS   65536
#define DD   256
#define KK   10
#define NCH  29          // sample chunks per class -> 290 CTAs (~2/SM)
#define SORT_T 4096      // 16 blocks x 256 sorting threads
#define SPT  16          // samples per sorting thread
#define NTILE 3          // (0,0),(0,1),(1,1) 128x128 tiles of 256x256
#define TRI_N 32896      // 256*257/2
#define SSTRIDE 264      // smem sample stride in floats (256+8): bank-perfect

typedef unsigned long long ull;

// ----------------- device scratch (static globals; no allocation) -----------------
__device__ int    g_hist[KK * SORT_T];
__device__ int    g_count[KK];
__device__ int    g_off[KK];
__device__ int    g_perm[NS];
__device__ float  g_part[NCH * KK * NTILE][16384];   // ~57 MB partial tiles
__device__ float  g_cov[KK][DD * DD];
__device__ float  g_gram[DD * DD];
__device__ double g_logdet[KK + 1];                  // [0]=gram, [1..10]=classes

// ----------------- f32x2 helpers (packed fp32 FMA, plain sm_103-legal) -----------------
__device__ __forceinline__ ull pk2(float x, float y) {
    ull d;
    asm("mov.b64 %0, {%1, %2};" : "=l"(d)
        : "r"(__float_as_uint(x)), "r"(__float_as_uint(y)));
    return d;
}
__device__ __forceinline__ ull ffma2(ull a, ull b, ull c) {
    ull d;
    asm("fma.rn.f32x2 %0, %1, %2, %3;" : "=l"(d) : "l"(a), "l"(b), "l"(c));
    return d;
}
__device__ __forceinline__ float2 upk2(ull d) {
    unsigned int lo, hi;
    asm("mov.b64 {%0, %1}, %2;" : "=r"(lo), "=r"(hi) : "l"(d));
    return make_float2(__uint_as_float(lo), __uint_as_float(hi));
}

__device__ __forceinline__ int tri(int i) { return (i * (i + 1)) >> 1; }

__device__ __forceinline__ uint32_t smem_u32(const void* p) {
    uint32_t a;
    asm("{ .reg .u64 t; cvta.to.shared.u64 t, %1; cvt.u32.u64 %0, t; }"
        : "=r"(a) : "l"(p));
    return a;
}
__device__ __forceinline__ void cp_async16(uint32_t dst, const void* src, int ssz) {
    asm volatile("cp.async.cg.shared.global [%0], [%1], 16, %2;"
                 :: "r"(dst), "l"(src), "r"(ssz) : "memory");
}
#define CP_COMMIT() asm volatile("cp.async.commit_group;" ::: "memory")
#define CP_WAIT0()  asm volatile("cp.async.wait_group 0;" ::: "memory")

__device__ __forceinline__ void mma_tf32(float d[4], const uint32_t a[4],
                                         uint32_t b0, uint32_t b1) {
    asm volatile(
        "mma.sync.aligned.m16n8k8.row.col.f32.tf32.tf32.f32 "
        "{%0,%1,%2,%3}, {%4,%5,%6,%7}, {%8,%9}, {%0,%1,%2,%3};"
        : "+f"(d[0]), "+f"(d[1]), "+f"(d[2]), "+f"(d[3])
        : "r"(a[0]), "r"(a[1]), "r"(a[2]), "r"(a[3]), "r"(b0), "r"(b1));
}

// Block-local int64-vs-int32 label detection (deterministic; every block
// derives the same answer from the first 2048 32-bit words of Y).
__device__ __forceinline__ int detect_is64_block(const int* __restrict__ Y,
                                                 int* sh_bad) {
    if (threadIdx.x == 0) *sh_bad = 0;
    __syncthreads();
    int viol = 0;
#pragma unroll
    for (int w = 0; w < 8; ++w) {
        int idx = (int)threadIdx.x * 8 + w;
        int v = Y[idx];
        if (idx & 1) { if (v != 0) viol = 1; }
        else         { if (v < 0 || v >= KK) viol = 1; }
    }
    if (viol) atomicOr(sh_bad, 1);
    __syncthreads();
    return (*sh_bad) ? 0 : 1;
}

// ----------------- 1-3. deterministic stable counting sort of labels -----------------
__global__ void k_hist(const int* __restrict__ Y) {
    __shared__ int sh_bad;
    int is64 = detect_is64_block(Y, &sh_bad);
    int t = blockIdx.x * blockDim.x + threadIdx.x;
    int cnt[KK];
#pragma unroll
    for (int c = 0; c < KK; ++c) cnt[c] = 0;
    int base = t * SPT;
    for (int q = 0; q < SPT; ++q) {
        int i = base + q;
        int lab = is64 ? Y[2 * i] : Y[i];
        cnt[lab]++;
    }
#pragma unroll
    for (int c = 0; c < KK; ++c) g_hist[c * SORT_T + t] = cnt[c];
}

__global__ void k_scan() {
    int c = blockIdx.x, tid = threadIdx.x;
    int* h = g_hist + c * SORT_T;
    int loc[16];
    int base = tid * 16;
    int tsum = 0;
#pragma unroll
    for (int q = 0; q < 16; ++q) { loc[q] = h[base + q]; tsum += loc[q]; }
    __shared__ int sh[256];
    sh[tid] = tsum;
    __syncthreads();
    for (int st = 1; st < 256; st <<= 1) {
        int v = 0;
        if (tid >= st) v = sh[tid - st];
        __syncthreads();
        if (tid >= st) sh[tid] += v;
        __syncthreads();
    }
    int run = sh[tid] - tsum;
#pragma unroll
    for (int q = 0; q < 16; ++q) { h[base + q] = run; run += loc[q]; }
    if (tid == 255) g_count[c] = sh[255];
}

// scatter; also publishes class offsets
__global__ void k_scat(const int* __restrict__ Y) {
    __shared__ int sh_bad;
    __shared__ int soff[KK];
    int is64 = detect_is64_block(Y, &sh_bad);
    if (threadIdx.x < KK) {
        int a = 0;
        for (int c = 0; c < (int)threadIdx.x; ++c) a += g_count[c];
        soff[threadIdx.x] = a;
        if (blockIdx.x == 0) g_off[threadIdx.x] = a;
    }
    __syncthreads();
    int t = blockIdx.x * blockDim.x + threadIdx.x;
    int cnt[KK];
#pragma unroll
    for (int c = 0; c < KK; ++c) cnt[c] = 0;
    int base = t * SPT;
    for (int q = 0; q < SPT; ++q) {
        int i = base + q;
        int lab = is64 ? Y[2 * i] : Y[i];
        int pos = soff[lab] + g_hist[lab * SORT_T + t] + cnt[lab];
        cnt[lab]++;
        g_perm[pos] = i;
    }
}

// ----------------- 4. grouped SYRK via mma.sync tf32 + cp.async pipeline --------
// Raw fp32 bits fed as tf32 (HW truncates); no cvt, no register staging.
// One __syncthreads per 16-sample stage; 2 CTAs/SM.
template<int NF4, int FLO4>
__device__ __forceinline__ void syrk_tile(
    const float4* __restrict__ X4, int sb, int se, int nblk,
    uint32_t sbase, const uint32_t* __restrict__ Ssm,
    int tid, int MbL, int NbL, int ncol,
    float* __restrict__ op, int gid, int tig)
{
    constexpr int NIT = NF4 / 16;     // 16B copies per thread per 16-sample stage

    float acc[2][8][4];
#pragma unroll
    for (int a = 0; a < 2; ++a)
#pragma unroll
        for (int n = 0; n < 8; ++n)
#pragma unroll
            for (int c = 0; c < 4; ++c) acc[a][n][c] = 0.f;

    auto issue = [&](int s) {
        uint32_t bufaddr = sbase + (uint32_t)(s & 1) * (16 * SSTRIDE * 4);
#pragma unroll
        for (int l = 0; l < NIT; ++l) {
            int idx = tid + 256 * l;
            int samp = idx / NF4, f4 = idx % NF4;
            int si = sb + 16 * s + samp;
            bool ok = (si < se);
            int sp = ok ? g_perm[si] : 0;
            const float4* src = X4 + (size_t)sp * 64 + FLO4 + f4;
            uint32_t dst = bufaddr + (uint32_t)(samp * SSTRIDE + 4 * f4) * 4;
            cp_async16(dst, src, ok ? 16 : 0);
        }
        CP_COMMIT();
    };

    if (nblk > 0) issue(0);

    for (int s = 0; s < nblk; ++s) {
        CP_WAIT0();
        __syncthreads();                 // stage-s data visible; compute s-1 done
        if (s + 1 < nblk) issue(s + 1);  // into buf (s+1)&1, freed by compute s-1
        const uint32_t* Sb = Ssm + (s & 1) * (16 * SSTRIDE);
#pragma unroll
        for (int kb = 0; kb < 16; kb += 8) {
            int r0 = (kb + tig) * SSTRIDE;
            int r1 = (kb + tig + 4) * SSTRIDE;
            uint32_t a[2][4];
#pragma unroll
            for (int mf = 0; mf < 2; ++mf) {
                int m0 = MbL + 16 * mf + gid;
                a[mf][0] = Sb[r0 + m0];
                a[mf][1] = Sb[r0 + m0 + 8];
                a[mf][2] = Sb[r1 + m0];
                a[mf][3] = Sb[r1 + m0 + 8];
            }
#pragma unroll
            for (int nb = 0; nb < 8; ++nb) {
                int n0 = NbL + 8 * nb + gid;
                uint32_t b0 = Sb[r0 + n0];
                uint32_t b1 = Sb[r1 + n0];
                mma_tf32(acc[0][nb], a[0], b0, b1);
                mma_tf32(acc[1][nb], a[1], b0, b1);
            }
        }
    }
    __syncthreads();                     // last-stage compute done before S reuse

    // epilogue: 32x64 warp region
#pragma unroll
    for (int mf = 0; mf < 2; ++mf) {
#pragma unroll
        for (int nb = 0; nb < 8; ++nb) {
            int row0 = MbL + 16 * mf + gid;
            int col = ncol + 8 * nb + 2 * tig;
            *(float2*)&op[row0 * 128 + col] =
                make_float2(acc[mf][nb][0], acc[mf][nb][1]);
            *(float2*)&op[(row0 + 8) * 128 + col] =
                make_float2(acc[mf][nb][2], acc[mf][nb][3]);
        }
    }
}

__global__ void __launch_bounds__(256, 2) k_syrk_mma(const float* __restrict__ X) {
    __shared__ uint32_t S[2][16 * SSTRIDE];

    int tid = threadIdx.x, wid = tid >> 5, lane = tid & 31;
    int gid = lane >> 2, tig = lane & 3;

    int b = blockIdx.x;
    int ch = b / KK, k = b % KK;
    int off = g_off[k], cnt = g_count[k];
    int len = (cnt + NCH - 1) / NCH;
    int sb = off + ch * len;
    int se = off + cnt;
    if (sb + len < se) se = sb + len;
    int nblk = (se > sb) ? (se - sb + 15) / 16 : 0;

    const float4* X4 = (const float4*)X;
    uint32_t sbase = smem_u32(S);
    const uint32_t* Ssm = &S[0][0];
    int mw = wid >> 1, nw = wid & 1;       // 4 x 2 warp grid
    int MbL = 32 * mw, ncol = 64 * nw;
    float* base_op = g_part[(ch * KK + k) * NTILE];

    syrk_tile<32, 0>(X4, sb, se, nblk, sbase, Ssm, tid, MbL, ncol, ncol,
                     base_op, gid, tig);
    syrk_tile<64, 0>(X4, sb, se, nblk, sbase, Ssm, tid, MbL, 128 + ncol, ncol,
                     base_op + 16384, gid, tig);
    syrk_tile<32, 32>(X4, sb, se, nblk, sbase, Ssm, tid, MbL, ncol, ncol,
                     base_op + 32768, gid, tig);
}

// ----------------- 5. reduce chunk partials -> full mirrored cov -----------------
__global__ void k_reduce() {
    int blk = blockIdx.x;              // KK*NTILE*4 blocks
    int r = blk >> 2, quad = blk & 3;
    int k = r / NTILE, t = r % NTILE;
    int tid = threadIdx.x;
    int e0 = quad * 4096;
    for (int e = e0 + tid; e < e0 + 4096; e += 256) {
        float sum = 0.f;
#pragma unroll
        for (int ch = 0; ch < NCH; ++ch) sum += g_part[ch * (KK * NTILE) + r][e];
        int i = e >> 7, j = e & 127;
        if (t == 0)      g_cov[k][i * DD + j] = sum;
        else if (t == 2) g_cov[k][(128 + i) * DD + 128 + j] = sum;
        else {
            g_cov[k][i * DD + 128 + j] = sum;
            g_cov[k][(128 + j) * DD + i] = sum;
        }
    }
}

__global__ void k_gram() {
    int e = blockIdx.x * 256 + threadIdx.x;
    float s = 0.f;
#pragma unroll
    for (int k = 0; k < KK; ++k) s += g_cov[k][e];
    g_gram[e] = s;
}

// ----------------- 6. blocked right-looking Cholesky + logdet (512 thr) ----------
__global__ void __launch_bounds__(512, 1) k_chol() {
    extern __shared__ float Ls[];    // TRI_N floats = 131584 bytes
    __shared__ float L11[16 * 16];
    __shared__ float inv11[16];
    __shared__ double red[512];

    int b = blockIdx.x;
    const float* A = (b == 0) ? g_gram : g_cov[b - 1];
    float s;
    if (b == 0) s = 256.0f / (65536.0f * 0.01f);
    else {
        double tr = (double)g_count[b - 1] + 1e-8;
        s = (float)(256.0 / (tr * 0.01));
    }
    int tid = threadIdx.x;
    int wid = tid >> 5, lane = tid & 31;

    // load I + s*A, packed lower triangle
    for (int p = tid; p < TRI_N; p += 512) {
        int i = (int)((sqrtf(8.f * (float)p + 1.f) - 1.f) * 0.5f);
        while (tri(i + 1) <= p) ++i;
        while (tri(i) > p) --i;
        int j = p - tri(i);
        Ls[p] = ((i == j) ? 1.f : 0.f) + s * A[i * DD + j];
    }
    __syncthreads();

    for (int j0 = 0; j0 < DD; j0 += 16) {
        // --- (A) diagonal block factor: warp 0, registers + shuffles ---
        if (wid == 0) {
            float x[16];
            int r = j0 + lane;
            if (lane < 16) {
#pragma unroll
                for (int q = 0; q < 16; ++q)
                    x[q] = (q <= lane) ? Ls[tri(r) + j0 + q] : 0.f;
            } else {
#pragma unroll
                for (int q = 0; q < 16; ++q) x[q] = 1.f;   // inert lanes
            }
#pragma unroll
            for (int c = 0; c < 16; ++c) {
                float piv = sqrtf(__shfl_sync(0xffffffffu, x[c], c));
                float iv = 1.f / piv;
                if (lane == c) x[c] = piv;
                else if (lane > c) x[c] *= iv;
#pragma unroll
                for (int q = c + 1; q < 16; ++q) {
                    float lqc = __shfl_sync(0xffffffffu, x[c], q);
                    if (lane >= q) x[q] -= x[c] * lqc;
                }
            }
            if (lane < 16) {
#pragma unroll
                for (int q = 0; q < 16; ++q)
                    if (q <= lane) {
                        Ls[tri(r) + j0 + q] = x[q];
                        L11[lane * 16 + q] = x[q];
                    }
                inv11[lane] = 1.f / x[lane];
            }
        }
        __syncthreads();

        // --- (B) TRSM: rows below panel, one row per thread, no bars inside ---
        for (int i = j0 + 16 + tid; i < DD; i += 512) {
            int base = tri(i) + j0;
            float x[16];
#pragma unroll
            for (int q = 0; q < 16; ++q) x[q] = Ls[base + q];
#pragma unroll
            for (int c = 0; c < 16; ++c) {
                float acc = x[c];
#pragma unroll
                for (int q = 0; q < c; ++q) acc -= L11[c * 16 + q] * x[q];
                x[c] = acc * inv11[c];
            }
#pragma unroll
            for (int q = 0; q < 16; ++q) Ls[base + q] = x[q];
        }
        __syncthreads();

        // --- (C) rank-16 trailing update: 4 warps per 64-col block ---
        {
            int v = wid >> 2, ph = wid & 3;
            int cb = j0 + 16 + 64 * v;
            int c = cb + 2 * lane;
            if (c < DD) {
                ull lcn[16];
                int tc0 = tri(c) + j0, tc1 = tri(c + 1) + j0;
#pragma unroll
                for (int q = 0; q < 16; ++q)
                    lcn[q] = pk2(-Ls[tc0 + q], -Ls[tc1 + q]);
                int cd = c - j0;
                for (int r0 = cb + 4 * ph; r0 < DD; r0 += 16) {
                    int base[4]; ull acc[4]; bool a0[4], a1[4];
#pragma unroll
                    for (int u = 0; u < 4; ++u) {
                        int r = r0 + u;
                        base[u] = tri(r) + j0;
                        a0[u] = (r >= c); a1[u] = (r > c);
                        float x0 = a0[u] ? Ls[base[u] + cd] : 0.f;
                        float x1 = a1[u] ? Ls[base[u] + cd + 1] : 0.f;
                        acc[u] = pk2(x0, x1);
                    }
#pragma unroll
                    for (int q = 0; q < 16; ++q) {
#pragma unroll
                        for (int u = 0; u < 4; ++u) {
                            float p = Ls[base[u] + q];   // broadcast across warp
                            acc[u] = ffma2(pk2(p, p), lcn[q], acc[u]);
                        }
                    }
#pragma unroll
                    for (int u = 0; u < 4; ++u) {
                        float2 res = upk2(acc[u]);
                        if (a0[u]) Ls[base[u] + cd] = res.x;
                        if (a1[u]) Ls[base[u] + cd + 1] = res.y;
                    }
                }
            }
        }
        __syncthreads();
    }

    // logdet = 2 * sum(ln L_ii), fp64 tree reduce (deterministic)
    red[tid] = (tid < DD) ? log((double)Ls[tri(tid) + tid]) : 0.0;
    __syncthreads();
    for (int st = 256; st > 0; st >>= 1) {
        if (tid < st) red[tid] += red[tid + st];
        __syncthreads();
    }
    if (tid == 0) g_logdet[b] = 2.0 * red[0];
}

// ----------------- 7. finalize -----------------
__global__ void k_final(float* out) {
    double disc = 0.5 * g_logdet[0];
    double comp = 0.0;
    for (int k = 0; k < KK; ++k) {
        double tr = (double)g_count[k] + 1e-8;
        comp += g_logdet[k + 1] * tr;
    }
    comp = comp / 65536.0 / 2.0;
    out[0] = (float)(-disc + comp);
    out[1] = (float)disc;
    out[2] = (float)comp;
    out[3] = (float)disc;
    out[4] = (float)comp;
}

// ----------------- host -----------------
extern "C" void kernel_launch(void* const* d_in, const int* in_sizes, int n_in,
                              void* d_out, int out_size) {
    const float* X = 0;
    const int* Y = 0;
    for (int i = 0; i < n_in; ++i) {
        if (in_sizes[i] == NS * DD) X = (const float*)d_in[i];
        else if (in_sizes[i] == NS) Y = (const int*)d_in[i];
    }
    if (!X) X = (const float*)d_in[0];
    if (!Y) Y = (const int*)d_in[1];
    float* out = (float*)d_out;

    k_hist<<<16, 256>>>(Y);
    k_scan<<<KK, 256>>>();
    k_scat<<<16, 256>>>(Y);
    k_syrk_mma<<<NCH * KK, 256>>>(X);     // launch idx 3 -> ncu captures this
    k_reduce<<<KK * NTILE * 4, 256>>>();
    k_gram<<<256, 256>>>();
    cudaFuncSetAttribute(k_chol, cudaFuncAttributeMaxDynamicSharedMemorySize,
                         TRI_N * (int)sizeof(float));
    k_chol<<<KK + 1, 512, TRI_N * sizeof(float)>>>();
    k_final<<<1, 1>>>(out);
    (void)out_size;
}